// round 15
// baseline (speedup 1.0000x reference)
#include <cuda_runtime.h>
#include <math.h>
#include <stdint.h>

#define N_SPK 65536
#define HID   1024
#define DUP   2048
#define UMAT  3072
#define LN_EPS 1e-5f

#define FUSED_BLOCKS 296                 // 148 SMs x 2 resident blocks (exact fit)
#define WARPS_TOTAL  (FUSED_BLOCKS * 8)  // 2368 persistent warps
#define CTX_BLOCKS   (FUSED_BLOCKS / 8)  // 37 combining blocks x 8 partials
#define H01_BLOCKS   512                 // side-stream W1 slices 0/1, 4 rows each

// ---- scratch (allocation-free: __device__ globals) ----
__device__ float g_query[HID];
__device__ float g_wm[FUSED_BLOCKS];              // per-BLOCK softmax max
__device__ float g_ws[FUSED_BLOCKS];              // per-BLOCK softmax sum
__device__ float g_wv[FUSED_BLOCKS * HID];        // per-BLOCK weighted vectors (1.2 MB)
__device__ float g_context[HID];
__device__ float g_hacc[DUP];                     // layer-1 pre-activations
__device__ float g_oacc[HID];                     // layer-2 partials
__device__ unsigned int g_tick = 0;               // monotonic grid barrier (reset by k_init)
__device__ unsigned int g_h01done = 0;            // k_h01 completion counter (reset by k_init)

__device__ __forceinline__ float warp_sum(float v) {
#pragma unroll
    for (int o = 16; o > 0; o >>= 1) v += __shfl_xor_sync(0xffffffffu, v, o);
    return v;
}
__device__ __forceinline__ float warp_max(float v) {
#pragma unroll
    for (int o = 16; o > 0; o >>= 1) v = fmaxf(v, __shfl_xor_sync(0xffffffffu, v, o));
    return v;
}
__device__ __forceinline__ float dot4(float4 a, float4 b) {
    return a.x * b.x + a.y * b.y + a.z * b.z + a.w * b.w;
}
__device__ __forceinline__ uint32_t smem_u32(const void* p) {
    return (uint32_t)__cvta_generic_to_shared(p);
}
__device__ __forceinline__ void cp_async16(uint32_t dst, const void* src) {
    asm volatile("cp.async.cg.shared.global [%0], [%1], 16;\n" :: "r"(dst), "l"(src));
}
__device__ __forceinline__ void cp_commit_wait_all() {
    asm volatile("cp.async.commit_group;\n");
    asm volatile("cp.async.wait_group 0;\n" ::: "memory");
}
__device__ __forceinline__ float gelu1(float x) {
    return 0.5f * x * (1.f + erff(x * 0.70710678118654752f));
}

// Grid barrier: monotonic counter, target = phase * FUSED_BLOCKS.
__device__ __forceinline__ void grid_bar(unsigned int target) {
    __threadfence();
    __syncthreads();
    if (threadIdx.x == 0) {
        atomicAdd(&g_tick, 1u);
        while (atomicAdd(&g_tick, 0u) < target) __nanosleep(64);
    }
    __syncthreads();
    __threadfence();
}

// K0: reset counters + zero the atomically-accumulated buffers.
__global__ void k_init() {
    int t = threadIdx.x;
    if (t == 0) { g_tick = 0; g_h01done = 0; }
    ((float4*)g_context)[t] = make_float4(0.f, 0.f, 0.f, 0.f);
    ((float4*)g_oacc)[t]    = make_float4(0.f, 0.f, 0.f, 0.f);
}

// K_h01 (side stream, launched FIRST): W1 slices 0+1 GEMV, 512 blocks x 4 rows.
// Both slices per block -> plain store to g_hacc (no atomics, no zero init).
__global__ void __launch_bounds__(256)
k_h01(const float* __restrict__ W1,
      const float* __restrict__ u_t, const float* __restrict__ SE,
      const int* __restrict__ s_i_p) {
    __shared__ float tileA[4 * HID];      // 16 KB slice 0
    __shared__ float tileB[4 * HID];      // 16 KB slice 1
    __shared__ float sm[32];
    int t = threadIdx.x;
    int lane = t & 31, warp = t >> 5;
    int row0 = blockIdx.x * 4;

#pragma unroll
    for (int r = 0; r < 4; r++)
        cp_async16(smem_u32(&tileA[r * HID + t * 4]),
                   W1 + (size_t)(row0 + r) * UMAT + t * 4);
#pragma unroll
    for (int r = 0; r < 4; r++)
        cp_async16(smem_u32(&tileB[r * HID + t * 4]),
                   W1 + (size_t)(row0 + r) * UMAT + 1024 + t * 4);

    float4 bu = ((const float4*)u_t)[t];
    float4 bs = ((const float4*)(SE + (size_t)(*s_i_p) * HID))[t];
    cp_commit_wait_all();
    __syncthreads();

    float p[4];
#pragma unroll
    for (int r = 0; r < 4; r++)
        p[r] = dot4(((const float4*)tileA)[r * 256 + t], bu)
             + dot4(((const float4*)tileB)[r * 256 + t], bs);
#pragma unroll
    for (int r = 0; r < 4; r++) {
        float v = warp_sum(p[r]);
        if (lane == 0) sm[r * 8 + warp] = v;
    }
    __syncthreads();
    if (t < 32) {
        float v = sm[t];
#pragma unroll
        for (int o = 4; o > 0; o >>= 1) v += __shfl_xor_sync(0xffffffffu, v, o, 8);
        if ((t & 7) == 0) g_hacc[row0 + (t >> 3)] = v;   // plain store
    }
    __threadfence();
    __syncthreads();
    if (t == 0) atomicAdd(&g_h01done, 1u);
}

// K_mega: everything else, phased by grid barriers.
//  P0: blocks 0..127 compute query (8 rows each)           -> bar(296)
//  P1: bank pass (copy + logits + online softmax partials) -> bar(592)
//  P2: blocks 0..36 combine g_context                      -> bar(888)
//  P3: blocks 0..255 wait h01, W1 slice-2 GEMV -> g_hacc   -> bar(1184)
//  P4: blocks 0..255 gelu + W2 GEMV -> g_oacc              -> bar(1480)
//  P5: block 0 LayerNorm + residual scatter
__global__ void __launch_bounds__(256, 2)
k_mega(const float* __restrict__ SE, float* __restrict__ out,
       const float* __restrict__ W_attn, const float* __restrict__ W1,
       const float* __restrict__ W2,
       const float* __restrict__ b1, const float* __restrict__ b2,
       const float* __restrict__ gamma, const float* __restrict__ beta,
       const int* __restrict__ s_i_p, const float* __restrict__ u_t) {
    __shared__ float q[HID];              // query; reused as h-slice in P4
    __shared__ float s_acc[HID];
    __shared__ float tile[8 * HID];       // 32 KB staging
    __shared__ float s_m[8], s_s[8];
    __shared__ float red[8];
    __shared__ float fin[2];
    __shared__ float e_sh[8];
    __shared__ float sm2[64];

    int t = threadIdx.x;
    int warp = t >> 5, lane = t & 31;
    int si = *s_i_p;

    // ================= P0: query GEMV (blocks 0..127) =================
    if (blockIdx.x < 128) {
        int row0 = blockIdx.x * 8;
#pragma unroll
        for (int r = 0; r < 8; r++)
            cp_async16(smem_u32(&tile[r * HID + t * 4]),
                       W_attn + (size_t)(row0 + r) * HID + t * 4);
        float4 b = ((const float4*)u_t)[t];
        cp_commit_wait_all();
        __syncthreads();

        float p[8];
#pragma unroll
        for (int r = 0; r < 8; r++) p[r] = dot4(((const float4*)tile)[r * 256 + t], b);
#pragma unroll
        for (int r = 0; r < 8; r++) {
            float v = warp_sum(p[r]);
            if (lane == 0) sm2[r * 8 + warp] = v;
        }
        __syncthreads();
        if (t < 64) {
            float v = sm2[t];
#pragma unroll
            for (int o = 4; o > 0; o >>= 1) v += __shfl_xor_sync(0xffffffffu, v, o, 8);
            if ((t & 7) == 0) g_query[row0 + (t >> 3)] = v;
        }
    }
    grid_bar(1 * FUSED_BLOCKS);

    // ================= P1: bank pass =================
    for (int i = t; i < HID; i += blockDim.x) q[i] = g_query[i];
    __syncthreads();

    int gw = blockIdx.x * 8 + warp;
    const float4* se4  = (const float4*)SE;
    float4*       out4 = (float4*)out;
    const float4* q4   = (const float4*)q;

    float4 v0[8], v1[8], acc[8];
#pragma unroll
    for (int k = 0; k < 8; k++) acc[k] = make_float4(0.f, 0.f, 0.f, 0.f);
    float m = -INFINITY, s = 0.f;

    {
        size_t rb = (size_t)gw * (HID / 4);
#pragma unroll
        for (int k = 0; k < 8; k++) v0[k] = __ldcs(&se4[rb + k * 32 + lane]);
    }

    for (int row = gw; row < N_SPK; row += WARPS_TOTAL) {
        size_t rb = (size_t)row * (HID / 4);
        int nrow = row + WARPS_TOTAL;
        if (nrow < N_SPK) {
            size_t nb = (size_t)nrow * (HID / 4);
#pragma unroll
            for (int k = 0; k < 8; k++) v1[k] = __ldcs(&se4[nb + k * 32 + lane]);
        }
        float p = 0.f;
#pragma unroll
        for (int k = 0; k < 8; k++) p += dot4(v0[k], q4[k * 32 + lane]);
        p = warp_sum(p);

        float mn = fmaxf(m, p);
        float sc = expf(m - mn);          // first iter: exp(-inf)=0
        float wt = expf(p - mn);
        s = s * sc + wt;
        m = mn;
#pragma unroll
        for (int k = 0; k < 8; k++) {
            __stcs(&out4[rb + k * 32 + lane], v0[k]);
            acc[k].x = fmaf(acc[k].x, sc, wt * v0[k].x);
            acc[k].y = fmaf(acc[k].y, sc, wt * v0[k].y);
            acc[k].z = fmaf(acc[k].z, sc, wt * v0[k].z);
            acc[k].w = fmaf(acc[k].w, sc, wt * v0[k].w);
        }
#pragma unroll
        for (int k = 0; k < 8; k++) v0[k] = v1[k];
    }

    // block-level merge of 8 warp partials
    if (lane == 0) { s_m[warp] = m; s_s[warp] = s; }
    __syncthreads();
    float Mb = s_m[0];
#pragma unroll
    for (int j = 1; j < 8; j++) Mb = fmaxf(Mb, s_m[j]);
    float Sb = 0.f;
#pragma unroll
    for (int j = 0; j < 8; j++) Sb += s_s[j] * expf(s_m[j] - Mb);
    float scw = expf(m - Mb);

    float4* sa4 = (float4*)s_acc;
    for (int w = 0; w < 8; w++) {
        if (warp == w) {
#pragma unroll
            for (int k = 0; k < 8; k++) {
                int c = k * 32 + lane;
                float4 r;
                if (w == 0) r = make_float4(0.f, 0.f, 0.f, 0.f);
                else        r = sa4[c];
                r.x += acc[k].x * scw;
                r.y += acc[k].y * scw;
                r.z += acc[k].z * scw;
                r.w += acc[k].w * scw;
                sa4[c] = r;
            }
        }
        __syncthreads();
    }

    if (t == 0) { g_wm[blockIdx.x] = Mb; g_ws[blockIdx.x] = Sb; }
    ((float4*)g_wv)[(size_t)blockIdx.x * (HID / 4) + t] = sa4[t];

    grid_bar(2 * FUSED_BLOCKS);

    // ================= P2: ctx combine (blocks 0..36) =================
    if (blockIdx.x < CTX_BLOCKS) {
        float m0 = (t < FUSED_BLOCKS) ? g_wm[t] : -INFINITY;
        float m1 = (t + 256 < FUSED_BLOCKS) ? g_wm[t + 256] : -INFINITY;
        float mm = fmaxf(m0, m1);
        mm = warp_max(mm);
        if (lane == 0) red[warp] = mm;
        __syncthreads();
        if (t < 32) {
            float x = (t < 8) ? red[t] : -INFINITY;
            x = warp_max(x);
            if (t == 0) fin[0] = x;
        }
        __syncthreads();
        float M = fin[0];

        float ss = 0.f;
        if (t < FUSED_BLOCKS)       ss += g_ws[t] * expf(m0 - M);
        if (t + 256 < FUSED_BLOCKS) ss += g_ws[t + 256] * expf(m1 - M);
        ss = warp_sum(ss);
        __syncthreads();
        if (lane == 0) red[warp] = ss;
        __syncthreads();
        if (t < 32) {
            float x = (t < 8) ? red[t] : 0.f;
            x = warp_sum(x);
            if (t == 0) fin[1] = x;
        }
        __syncthreads();
        float invS = 1.f / fin[1];

        int wbase = blockIdx.x * 8;
        if (t < 8) e_sh[t] = expf(g_wm[wbase + t] - M) * invS;
        __syncthreads();

        const float4* v4 = (const float4*)g_wv;
        float4 accc = make_float4(0.f, 0.f, 0.f, 0.f);
#pragma unroll
        for (int j = 0; j < 8; j++) {
            float4 v = v4[(size_t)(wbase + j) * (HID / 4) + t];
            float ee = e_sh[j];
            accc.x = fmaf(ee, v.x, accc.x);
            accc.y = fmaf(ee, v.y, accc.y);
            accc.z = fmaf(ee, v.z, accc.z);
            accc.w = fmaf(ee, v.w, accc.w);
        }
        float* ctx = g_context + t * 4;
        atomicAdd(ctx + 0, accc.x);
        atomicAdd(ctx + 1, accc.y);
        atomicAdd(ctx + 2, accc.z);
        atomicAdd(ctx + 3, accc.w);
    }

    grid_bar(3 * FUSED_BLOCKS);

    // ================= P3: W1 slice-2 GEMV (blocks 0..255) =================
    if (blockIdx.x < 256) {
        // wait for side-stream k_h01 plain stores (long done by now)
        if (t == 0) {
            while (atomicAdd(&g_h01done, 0u) < H01_BLOCKS) __nanosleep(64);
        }
        __syncthreads();
        __threadfence();

        int row0 = blockIdx.x * 8;
#pragma unroll
        for (int r = 0; r < 8; r++)
            cp_async16(smem_u32(&tile[r * HID + t * 4]),
                       W1 + (size_t)(row0 + r) * UMAT + 2048 + t * 4);
        float4 b = ((const float4*)g_context)[t];
        cp_commit_wait_all();
        __syncthreads();

        float p[8];
#pragma unroll
        for (int r = 0; r < 8; r++) p[r] = dot4(((const float4*)tile)[r * 256 + t], b);
#pragma unroll
        for (int r = 0; r < 8; r++) {
            float v = warp_sum(p[r]);
            if (lane == 0) sm2[r * 8 + warp] = v;
        }
        __syncthreads();
        if (t < 64) {
            float v = sm2[t];
#pragma unroll
            for (int o = 4; o > 0; o >>= 1) v += __shfl_xor_sync(0xffffffffu, v, o, 8);
            if ((t & 7) == 0) atomicAdd(&g_hacc[row0 + (t >> 3)], v);
        }
    }

    grid_bar(4 * FUSED_BLOCKS);

    // ================= P4: gelu + W2 GEMV (blocks 0..255) =================
    if (blockIdx.x < 256) {
        int slice = blockIdx.x >> 7;      // 0..1
        int rg    = blockIdx.x & 127;     // 0..127
        int row0  = rg * 8;
#pragma unroll
        for (int r = 0; r < 8; r++)
            cp_async16(smem_u32(&tile[r * HID + t * 4]),
                       W2 + (size_t)(row0 + r) * DUP + slice * 1024 + t * 4);
        {
            float4 aa = ((const float4*)g_hacc)[slice * 256 + t];
            float4 bb = ((const float4*)b1)[slice * 256 + t];
            float4 r;
            r.x = gelu1(aa.x + bb.x);
            r.y = gelu1(aa.y + bb.y);
            r.z = gelu1(aa.z + bb.z);
            r.w = gelu1(aa.w + bb.w);
            ((float4*)q)[t] = r;          // reuse q smem as h-slice
        }
        cp_commit_wait_all();
        __syncthreads();

        float4 b = ((const float4*)q)[t];
        float p[8];
#pragma unroll
        for (int r = 0; r < 8; r++) p[r] = dot4(((const float4*)tile)[r * 256 + t], b);
#pragma unroll
        for (int r = 0; r < 8; r++) {
            float v = warp_sum(p[r]);
            if (lane == 0) sm2[r * 8 + warp] = v;
        }
        __syncthreads();
        if (t < 64) {
            float v = sm2[t];
#pragma unroll
            for (int o = 4; o > 0; o >>= 1) v += __shfl_xor_sync(0xffffffffu, v, o, 8);
            if ((t & 7) == 0) atomicAdd(&g_oacc[row0 + (t >> 3)], v);
        }
    }

    grid_bar(5 * FUSED_BLOCKS);

    // ================= P5: LayerNorm + scatter (block 0) =================
    if (blockIdx.x != 0) return;

    float4 oa = ((const float4*)g_oacc)[t];
    float4 ob = ((const float4*)b2)[t];
    float o0 = oa.x + ob.x, o1 = oa.y + ob.y, o2 = oa.z + ob.z, o3 = oa.w + ob.w;

    float lsum = o0 + o1 + o2 + o3;
    {
        float v = warp_sum(lsum);
        if (lane == 0) red[warp] = v;
        __syncthreads();
        if (t < 32) {
            float x = (t < 8) ? red[t] : 0.f;
            x = warp_sum(x);
            if (t == 0) fin[0] = x * (1.f / 1024.f);
        }
        __syncthreads();
    }
    float mu = fin[0];
    float d0 = o0 - mu, d1 = o1 - mu, d2 = o2 - mu, d3 = o3 - mu;
    float lvar = d0 * d0 + d1 * d1 + d2 * d2 + d3 * d3;
    {
        float v = warp_sum(lvar);
        __syncthreads();
        if (lane == 0) red[warp] = v;
        __syncthreads();
        if (t < 32) {
            float x = (t < 8) ? red[t] : 0.f;
            x = warp_sum(x);
            if (t == 0) fin[1] = rsqrtf(x * (1.f / 1024.f) + LN_EPS);
        }
        __syncthreads();
    }
    float rstd = fin[1];

    float4 gg = ((const float4*)gamma)[t];
    float4 bbt = ((const float4*)beta)[t];
    float4 hs = ((const float4*)(SE + (size_t)si * HID))[t];
    float4 r;
    r.x = hs.x + d0 * rstd * gg.x + bbt.x;
    r.y = hs.y + d1 * rstd * gg.y + bbt.y;
    r.z = hs.z + d2 * rstd * gg.z + bbt.z;
    r.w = hs.w + d3 * rstd * gg.w + bbt.w;
    ((float4*)(out + (size_t)si * HID))[t] = r;
}

extern "C" void kernel_launch(void* const* d_in, const int* in_sizes, int n_in,
                              void* d_out, int out_size) {
    const float* u_t    = (const float*)d_in[0];
    const float* SE     = (const float*)d_in[1];
    const float* W_attn = (const float*)d_in[2];
    const float* W1     = (const float*)d_in[3];
    const float* b1     = (const float*)d_in[4];
    const float* W2     = (const float*)d_in[5];
    const float* b2     = (const float*)d_in[6];
    const float* gamma  = (const float*)d_in[7];
    const float* beta   = (const float*)d_in[8];
    const int*   s_i    = (const int*)d_in[9];
    float* out = (float*)d_out;

    static cudaStream_t s_side = nullptr;
    static cudaEvent_t  ev_fork = nullptr, ev_join = nullptr;
    if (s_side == nullptr) {
        cudaStreamCreateWithFlags(&s_side, cudaStreamNonBlocking);
        cudaEventCreateWithFlags(&ev_fork, cudaEventDisableTiming);
        cudaEventCreateWithFlags(&ev_join, cudaEventDisableTiming);
    }

    // main: reset counters / zero atomically-accumulated buffers
    k_init<<<1, 256>>>();
    cudaEventRecord(ev_fork, 0);

    // side (submitted BEFORE mega -> FIFO dispatch schedules it first):
    // W1 slices 0/1 GEMV, overlapped with mega's bank pass
    cudaStreamWaitEvent(s_side, ev_fork, 0);
    k_h01<<<H01_BLOCKS, 256, 0, s_side>>>(W1, u_t, SE, s_i);
    cudaEventRecord(ev_join, s_side);

    // main: megakernel (query -> bank pass -> ctx -> slice2 -> W2 -> LN)
    k_mega<<<FUSED_BLOCKS, 256>>>(SE, out, W_attn, W1, W2,
                                  b1, b2, gamma, beta, s_i, u_t);
    cudaStreamWaitEvent(0, ev_join, 0);
}

// round 16
// speedup vs baseline: 1.0396x; 1.0396x over previous
#include <cuda_runtime.h>
#include <math.h>
#include <stdint.h>

#define N_SPK 65536
#define HID   1024
#define DUP   2048
#define UMAT  3072
#define LN_EPS 1e-5f

#define FUSED_BLOCKS 296                 // 148 SMs x 2 resident (exact fit)
#define WARPS_TOTAL  (FUSED_BLOCKS * 8)
#define CTX_BLOCKS   (FUSED_BLOCKS / 8)  // 37 combining blocks x 8 partials
#define H01_BLOCKS   512
#define TAIL_BLOCKS  256                 // <= 296 -> all co-resident, barriers safe

// ---- scratch (allocation-free: __device__ globals) ----
__device__ float g_query[HID];
__device__ float g_wm[FUSED_BLOCKS];
__device__ float g_ws[FUSED_BLOCKS];
__device__ float g_wv[FUSED_BLOCKS * HID];        // 1.2 MB partial vectors
__device__ float g_context[HID];
__device__ float g_hacc[DUP];                     // layer-1 pre-activations
__device__ float g_oacc[HID];                     // layer-2 partials
__device__ unsigned int g_tickF = 0;              // fused last-block election
__device__ unsigned int g_tickT = 0;              // tail grid barrier
__device__ float g_M, g_S;                        // global softmax max / sum

__device__ __forceinline__ float warp_sum(float v) {
#pragma unroll
    for (int o = 16; o > 0; o >>= 1) v += __shfl_xor_sync(0xffffffffu, v, o);
    return v;
}
__device__ __forceinline__ float warp_max(float v) {
#pragma unroll
    for (int o = 16; o > 0; o >>= 1) v = fmaxf(v, __shfl_xor_sync(0xffffffffu, v, o));
    return v;
}
__device__ __forceinline__ float dot4(float4 a, float4 b) {
    return a.x * b.x + a.y * b.y + a.z * b.z + a.w * b.w;
}
__device__ __forceinline__ uint32_t smem_u32(const void* p) {
    return (uint32_t)__cvta_generic_to_shared(p);
}
__device__ __forceinline__ void cp_async16(uint32_t dst, const void* src) {
    asm volatile("cp.async.cg.shared.global [%0], [%1], 16;\n" :: "r"(dst), "l"(src));
}
__device__ __forceinline__ void cp_commit() {
    asm volatile("cp.async.commit_group;\n");
}
__device__ __forceinline__ void cp_wait_all() {
    asm volatile("cp.async.wait_group 0;\n" ::: "memory");
}
__device__ __forceinline__ float gelu1(float x) {
    return 0.5f * x * (1.f + erff(x * 0.70710678118654752f));
}

// K1: query = W_attn @ u_t (128 blocks x 8 rows). Also zeros accumulators
// and both device counters. Does NOT touch g_hacc (h01 plain-stores it).
__global__ void k_query(const float* __restrict__ W_attn, const float* __restrict__ u_t) {
    __shared__ float tile[8 * HID];
    __shared__ float sm[64];
    int gt = blockIdx.x * 256 + threadIdx.x;
    if (gt < HID) g_context[gt] = 0.f;
    if (gt < HID) g_oacc[gt] = 0.f;
    if (gt == 0) { g_tickF = 0; g_tickT = 0; }

    int t = threadIdx.x;
    int lane = t & 31, wid = t >> 5;
    int row0 = blockIdx.x * 8;

#pragma unroll
    for (int r = 0; r < 8; r++)
        cp_async16(smem_u32(&tile[r * HID + t * 4]),
                   W_attn + (size_t)(row0 + r) * HID + t * 4);
    float4 b = ((const float4*)u_t)[t];
    cp_commit(); cp_wait_all();
    __syncthreads();

    float p[8];
#pragma unroll
    for (int r = 0; r < 8; r++) p[r] = dot4(((const float4*)tile)[r * 256 + t], b);
#pragma unroll
    for (int r = 0; r < 8; r++) {
        float v = warp_sum(p[r]);
        if (lane == 0) sm[r * 8 + wid] = v;
    }
    __syncthreads();
    if (t < 64) {
        float v = sm[t];
#pragma unroll
        for (int o = 4; o > 0; o >>= 1) v += __shfl_xor_sync(0xffffffffu, v, o, 8);
        if ((t & 7) == 0) g_query[row0 + (t >> 3)] = v;
    }
}

// K_h01 (side stream): W1 slices 0+1 GEMV, 512 blocks x 4 rows.
// Both slices per block -> plain store to g_hacc (no atomics, no zero init).
__global__ void __launch_bounds__(256)
k_h01(const float* __restrict__ W1,
      const float* __restrict__ u_t, const float* __restrict__ SE,
      const int* __restrict__ s_i_p) {
    __shared__ float tileA[4 * HID];
    __shared__ float tileB[4 * HID];
    __shared__ float sm[32];
    int t = threadIdx.x;
    int lane = t & 31, warp = t >> 5;
    int row0 = blockIdx.x * 4;

#pragma unroll
    for (int r = 0; r < 4; r++)
        cp_async16(smem_u32(&tileA[r * HID + t * 4]),
                   W1 + (size_t)(row0 + r) * UMAT + t * 4);
#pragma unroll
    for (int r = 0; r < 4; r++)
        cp_async16(smem_u32(&tileB[r * HID + t * 4]),
                   W1 + (size_t)(row0 + r) * UMAT + 1024 + t * 4);

    float4 bu = ((const float4*)u_t)[t];
    float4 bs = ((const float4*)(SE + (size_t)(*s_i_p) * HID))[t];
    cp_commit(); cp_wait_all();
    __syncthreads();

    float p[4];
#pragma unroll
    for (int r = 0; r < 4; r++)
        p[r] = dot4(((const float4*)tileA)[r * 256 + t], bu)
             + dot4(((const float4*)tileB)[r * 256 + t], bs);
#pragma unroll
    for (int r = 0; r < 4; r++) {
        float v = warp_sum(p[r]);
        if (lane == 0) sm[r * 8 + warp] = v;
    }
    __syncthreads();
    if (t < 32) {
        float v = sm[t];
#pragma unroll
        for (int o = 4; o > 0; o >>= 1) v += __shfl_xor_sync(0xffffffffu, v, o, 8);
        if ((t & 7) == 0) g_hacc[row0 + (t >> 3)] = v;   // plain store
    }
}

// K_fused: barrier-free bank pass (copy + logits + online-softmax partials).
// Last-arriving block reduces the 296 (m, s) pairs into g_M / g_S.
__global__ void __launch_bounds__(256, 2)
k_fused(const float* __restrict__ SE, float* __restrict__ out) {
    __shared__ float q[HID];
    __shared__ float s_acc[HID];
    __shared__ float s_m[8], s_s[8];
    __shared__ int s_last;
    __shared__ float red[8];
    for (int i = threadIdx.x; i < HID; i += blockDim.x) q[i] = g_query[i];
    __syncthreads();

    int warp = threadIdx.x >> 5, lane = threadIdx.x & 31;
    int gw = blockIdx.x * 8 + warp;

    const float4* se4  = (const float4*)SE;
    float4*       out4 = (float4*)out;
    const float4* q4   = (const float4*)q;

    float4 v0[8], v1[8], acc[8];
#pragma unroll
    for (int k = 0; k < 8; k++) acc[k] = make_float4(0.f, 0.f, 0.f, 0.f);
    float m = -INFINITY, s = 0.f;

    {
        size_t rb = (size_t)gw * (HID / 4);
#pragma unroll
        for (int k = 0; k < 8; k++) v0[k] = __ldcs(&se4[rb + k * 32 + lane]);
    }

    for (int row = gw; row < N_SPK; row += WARPS_TOTAL) {
        size_t rb = (size_t)row * (HID / 4);
        int nrow = row + WARPS_TOTAL;
        if (nrow < N_SPK) {
            size_t nb = (size_t)nrow * (HID / 4);
#pragma unroll
            for (int k = 0; k < 8; k++) v1[k] = __ldcs(&se4[nb + k * 32 + lane]);
        }
        float p = 0.f;
#pragma unroll
        for (int k = 0; k < 8; k++) p += dot4(v0[k], q4[k * 32 + lane]);
        p = warp_sum(p);

        float mn = fmaxf(m, p);
        float sc = expf(m - mn);          // first iter: exp(-inf)=0
        float wt = expf(p - mn);
        s = s * sc + wt;
        m = mn;
#pragma unroll
        for (int k = 0; k < 8; k++) {
            __stcs(&out4[rb + k * 32 + lane], v0[k]);
            acc[k].x = fmaf(acc[k].x, sc, wt * v0[k].x);
            acc[k].y = fmaf(acc[k].y, sc, wt * v0[k].y);
            acc[k].z = fmaf(acc[k].z, sc, wt * v0[k].z);
            acc[k].w = fmaf(acc[k].w, sc, wt * v0[k].w);
        }
#pragma unroll
        for (int k = 0; k < 8; k++) v0[k] = v1[k];
    }

    // block-level merge of 8 warp partials
    if (lane == 0) { s_m[warp] = m; s_s[warp] = s; }
    __syncthreads();
    float Mb = s_m[0];
#pragma unroll
    for (int j = 1; j < 8; j++) Mb = fmaxf(Mb, s_m[j]);
    float Sb = 0.f;
#pragma unroll
    for (int j = 0; j < 8; j++) Sb += s_s[j] * expf(s_m[j] - Mb);
    float scw = expf(m - Mb);

    float4* sa4 = (float4*)s_acc;
    for (int w = 0; w < 8; w++) {
        if (warp == w) {
#pragma unroll
            for (int k = 0; k < 8; k++) {
                int c = k * 32 + lane;
                float4 r;
                if (w == 0) r = make_float4(0.f, 0.f, 0.f, 0.f);
                else        r = sa4[c];
                r.x += acc[k].x * scw;
                r.y += acc[k].y * scw;
                r.z += acc[k].z * scw;
                r.w += acc[k].w * scw;
                sa4[c] = r;
            }
        }
        __syncthreads();
    }

    int t = threadIdx.x;
    if (t == 0) { g_wm[blockIdx.x] = Mb; g_ws[blockIdx.x] = Sb; }
    ((float4*)g_wv)[(size_t)blockIdx.x * (HID / 4) + t] = sa4[t];

    // last-block election: reduce global M, S (never blocks other blocks)
    __threadfence();
    __syncthreads();
    if (t == 0) {
        unsigned int tk = atomicAdd(&g_tickF, 1u);
        s_last = (tk == FUSED_BLOCKS - 1) ? 1 : 0;
    }
    __syncthreads();
    if (s_last) {
        float m0 = (t < FUSED_BLOCKS) ? g_wm[t] : -INFINITY;
        float m1 = (t + 256 < FUSED_BLOCKS) ? g_wm[t + 256] : -INFINITY;
        float mm = fmaxf(m0, m1);
        mm = warp_max(mm);
        if (lane == 0) red[t >> 5] = mm;
        __syncthreads();
        if (t < 32) {
            float x = (t < 8) ? red[t] : -INFINITY;
            x = warp_max(x);
            if (t == 0) red[0] = x;
        }
        __syncthreads();
        float M = red[0];
        float ss = 0.f;
        if (t < FUSED_BLOCKS)       ss += g_ws[t] * expf(m0 - M);
        if (t + 256 < FUSED_BLOCKS) ss += g_ws[t + 256] * expf(m1 - M);
        ss = warp_sum(ss);
        __syncthreads();
        if (lane == 0) red[t >> 5] = ss;
        __syncthreads();
        if (t < 32) {
            float x = (t < 8) ? red[t] : 0.f;
            x = warp_sum(x);
            if (t == 0) { g_M = M; g_S = x; }
        }
    }
}

// K_tail: ONE kernel for the whole MLP tail. 256 blocks, all co-resident.
//  entry: cp.async BOTH weight tiles (W1 slice-2 + W2 slice) into dyn smem
//  ctx combine (blocks 0..36, using g_M/g_S)        -> bar(256)
//  W1 slice-2 dot vs g_context -> atomicAdd g_hacc  -> bar(512)
//  gelu(g_hacc+b1) slice + W2 dot -> g_oacc          -> bar(768)
//  block 0: LayerNorm + residual scatter
__global__ void __launch_bounds__(256)
k_tail(const float* __restrict__ W1, const float* __restrict__ W2,
       const float* __restrict__ b1, const float* __restrict__ b2,
       const float* __restrict__ gamma, const float* __restrict__ beta,
       const int* __restrict__ s_i_p, const float* __restrict__ SE,
       float* __restrict__ out) {
    extern __shared__ float dyn[];        // [0:8K) W1s2 tile, [8K:16K) W2 tile (floats)
    float* tileA = dyn;
    float* tileB = dyn + 8 * HID;
    __shared__ float hsl[HID];
    __shared__ float e_sh[8];
    __shared__ float red[8];
    __shared__ float fin[2];
    __shared__ float sm2[64];

    int t = threadIdx.x;
    int warp = t >> 5, lane = t & 31;

    // ---- issue ALL weight loads immediately (no dependencies) ----
    int rowA = blockIdx.x * 8;            // W1 slice-2 rows
#pragma unroll
    for (int r = 0; r < 8; r++)
        cp_async16(smem_u32(&tileA[r * HID + t * 4]),
                   W1 + (size_t)(rowA + r) * UMAT + 2048 + t * 4);
    int slice = blockIdx.x >> 7;          // W2: 0..1
    int rowB  = (blockIdx.x & 127) * 8;
#pragma unroll
    for (int r = 0; r < 8; r++)
        cp_async16(smem_u32(&tileB[r * HID + t * 4]),
                   W2 + (size_t)(rowB + r) * DUP + slice * 1024 + t * 4);
    cp_commit();

    // ---- ctx combine (blocks 0..36), overlapped with the cp.asyncs ----
    if (blockIdx.x < CTX_BLOCKS) {
        int wbase = blockIdx.x * 8;
        if (t < 8) e_sh[t] = expf(g_wm[wbase + t] - g_M) / g_S;
        __syncthreads();
        const float4* v4 = (const float4*)g_wv;
        float4 accc = make_float4(0.f, 0.f, 0.f, 0.f);
#pragma unroll
        for (int j = 0; j < 8; j++) {
            float4 v = __ldcs(&v4[(size_t)(wbase + j) * (HID / 4) + t]);
            float ee = e_sh[j];
            accc.x = fmaf(ee, v.x, accc.x);
            accc.y = fmaf(ee, v.y, accc.y);
            accc.z = fmaf(ee, v.z, accc.z);
            accc.w = fmaf(ee, v.w, accc.w);
        }
        float* ctx = g_context + t * 4;
        atomicAdd(ctx + 0, accc.x);
        atomicAdd(ctx + 1, accc.y);
        atomicAdd(ctx + 2, accc.z);
        atomicAdd(ctx + 3, accc.w);
    }

    // ---- bar 1: context complete ----
    __threadfence();
    __syncthreads();
    if (t == 0) {
        atomicAdd(&g_tickT, 1u);
        while (atomicAdd(&g_tickT, 0u) < 1 * TAIL_BLOCKS) __nanosleep(32);
    }
    __syncthreads();
    __threadfence();

    // ---- W1 slice-2 GEMV (tiles already resident) ----
    cp_wait_all();
    __syncthreads();
    {
        float4 b = ((const float4*)g_context)[t];
        float p[8];
#pragma unroll
        for (int r = 0; r < 8; r++) p[r] = dot4(((const float4*)tileA)[r * 256 + t], b);
#pragma unroll
        for (int r = 0; r < 8; r++) {
            float v = warp_sum(p[r]);
            if (lane == 0) sm2[r * 8 + warp] = v;
        }
        __syncthreads();
        if (t < 64) {
            float v = sm2[t];
#pragma unroll
            for (int o = 4; o > 0; o >>= 1) v += __shfl_xor_sync(0xffffffffu, v, o, 8);
            if ((t & 7) == 0) atomicAdd(&g_hacc[rowA + (t >> 3)], v);
        }
    }

    // ---- bar 2: g_hacc complete ----
    __threadfence();
    __syncthreads();
    if (t == 0) {
        atomicAdd(&g_tickT, 1u);
        while (atomicAdd(&g_tickT, 0u) < 2 * TAIL_BLOCKS) __nanosleep(32);
    }
    __syncthreads();
    __threadfence();

    // ---- gelu + W2 GEMV ----
    {
        float4 aa = ((const float4*)g_hacc)[slice * 256 + t];
        float4 bb = ((const float4*)b1)[slice * 256 + t];
        float4 r;
        r.x = gelu1(aa.x + bb.x);
        r.y = gelu1(aa.y + bb.y);
        r.z = gelu1(aa.z + bb.z);
        r.w = gelu1(aa.w + bb.w);
        ((float4*)hsl)[t] = r;
        __syncthreads();

        float4 b = ((const float4*)hsl)[t];
        float p[8];
#pragma unroll
        for (int r = 0; r < 8; r++) p[r] = dot4(((const float4*)tileB)[r * 256 + t], b);
#pragma unroll
        for (int r = 0; r < 8; r++) {
            float v = warp_sum(p[r]);
            if (lane == 0) sm2[r * 8 + warp] = v;
        }
        __syncthreads();
        if (t < 64) {
            float v = sm2[t];
#pragma unroll
            for (int o = 4; o > 0; o >>= 1) v += __shfl_xor_sync(0xffffffffu, v, o, 8);
            if ((t & 7) == 0) atomicAdd(&g_oacc[rowB + (t >> 3)], v);
        }
    }

    // ---- bar 3: g_oacc complete ----
    __threadfence();
    __syncthreads();
    if (t == 0) {
        atomicAdd(&g_tickT, 1u);
        while (atomicAdd(&g_tickT, 0u) < 3 * TAIL_BLOCKS) __nanosleep(32);
    }
    __syncthreads();
    __threadfence();

    if (blockIdx.x != 0) return;

    // ---- LayerNorm + residual scatter (block 0) ----
    int si = *s_i_p;
    float4 oa = ((const float4*)g_oacc)[t];
    float4 ob = ((const float4*)b2)[t];
    float o0 = oa.x + ob.x, o1 = oa.y + ob.y, o2 = oa.z + ob.z, o3 = oa.w + ob.w;

    float lsum = o0 + o1 + o2 + o3;
    {
        float v = warp_sum(lsum);
        if (lane == 0) red[warp] = v;
        __syncthreads();
        if (t < 32) {
            float x = (t < 8) ? red[t] : 0.f;
            x = warp_sum(x);
            if (t == 0) fin[0] = x * (1.f / 1024.f);
        }
        __syncthreads();
    }
    float mu = fin[0];
    float d0 = o0 - mu, d1 = o1 - mu, d2 = o2 - mu, d3 = o3 - mu;
    float lvar = d0 * d0 + d1 * d1 + d2 * d2 + d3 * d3;
    {
        float v = warp_sum(lvar);
        __syncthreads();
        if (lane == 0) red[warp] = v;
        __syncthreads();
        if (t < 32) {
            float x = (t < 8) ? red[t] : 0.f;
            x = warp_sum(x);
            if (t == 0) fin[1] = rsqrtf(x * (1.f / 1024.f) + LN_EPS);
        }
        __syncthreads();
    }
    float rstd = fin[1];

    float4 gg = ((const float4*)gamma)[t];
    float4 bbt = ((const float4*)beta)[t];
    float4 hs = ((const float4*)(SE + (size_t)si * HID))[t];
    float4 r;
    r.x = hs.x + d0 * rstd * gg.x + bbt.x;
    r.y = hs.y + d1 * rstd * gg.y + bbt.y;
    r.z = hs.z + d2 * rstd * gg.z + bbt.z;
    r.w = hs.w + d3 * rstd * gg.w + bbt.w;
    ((float4*)(out + (size_t)si * HID))[t] = r;
}

extern "C" void kernel_launch(void* const* d_in, const int* in_sizes, int n_in,
                              void* d_out, int out_size) {
    const float* u_t    = (const float*)d_in[0];
    const float* SE     = (const float*)d_in[1];
    const float* W_attn = (const float*)d_in[2];
    const float* W1     = (const float*)d_in[3];
    const float* b1     = (const float*)d_in[4];
    const float* W2     = (const float*)d_in[5];
    const float* b2     = (const float*)d_in[6];
    const float* gamma  = (const float*)d_in[7];
    const float* beta   = (const float*)d_in[8];
    const int*   s_i    = (const int*)d_in[9];
    float* out = (float*)d_out;

    static cudaStream_t s_side = nullptr;
    static cudaEvent_t  ev_fork = nullptr, ev_join = nullptr;
    if (s_side == nullptr) {
        cudaStreamCreateWithFlags(&s_side, cudaStreamNonBlocking);
        cudaEventCreateWithFlags(&ev_fork, cudaEventDisableTiming);
        cudaEventCreateWithFlags(&ev_join, cudaEventDisableTiming);
        cudaFuncSetAttribute(k_tail, cudaFuncAttributeMaxDynamicSharedMemorySize,
                             16 * HID * (int)sizeof(float));
    }

    // main: query (+ counter/accumulator reset)
    k_query<<<HID / 8, 256>>>(W_attn, u_t);
    cudaEventRecord(ev_fork, 0);

    // side: W1 slices 0/1 GEMV, overlapped with the barrier-free bank pass
    cudaStreamWaitEvent(s_side, ev_fork, 0);
    k_h01<<<H01_BLOCKS, 256, 0, s_side>>>(W1, u_t, SE, s_i);
    cudaEventRecord(ev_join, s_side);

    // main: bank pass (emits g_M/g_S via last-block election)
    k_fused<<<FUSED_BLOCKS, 256>>>(SE, out);

    // join h01 (finished ~60us earlier; free), then the single tail kernel
    cudaStreamWaitEvent(0, ev_join, 0);
    k_tail<<<TAIL_BLOCKS, 256, 16 * HID * sizeof(float)>>>(
        W1, W2, b1, b2, gamma, beta, s_i, SE, out);
}